// round 8
// baseline (speedup 1.0000x reference)
#include <cuda_runtime.h>
#include <cuda_fp16.h>
#include <cstdint>

#define B_DIM 16
#define S_DIM 2048
#define I_DIM 1024
#define H_DIM 1024
#define M_TOTAL (B_DIM * S_DIM)   // 32768

#define BM 128
#define BN 128
#define KIT 32                    // K iterations of 32 halves each
#define THREADS 128
#define STAGES 4
#define STAGE_U32 4096            // A: 2048 u32 (128x32 half) + B: 2048 u32
#define SMEM_BYTES (STAGES * STAGE_U32 * 4)   // 64 KB dynamic

// Pre-permuted half buffers: row r, k-block kb (32 halves = 16 pairs),
// pair q at u32 position P(q) = 4*(q&3) + (q>>2) within the 16-u32 block.
// Lane tg LDS.128 at offset 4*tg -> pairs {tg, tg+4, tg+8, tg+12} =
// the m16n8k16 A/B fragments for both k-steps.
__device__ uint32_t g_xh[(size_t)M_TOTAL * I_DIM / 2];   // 64 MB
__device__ uint32_t g_wh[(size_t)H_DIM * I_DIM / 2];     // 2 MB
__device__ float    g_hterm[B_DIM * H_DIM];

// ---------------- helpers ----------------
__device__ __forceinline__ uint32_t smem_u32(const void* p) {
    uint32_t a;
    asm("{ .reg .u64 t; cvta.to.shared.u64 t, %1; cvt.u32.u64 %0, t; }" : "=r"(a) : "l"(p));
    return a;
}

__device__ __forceinline__ float tanh_fast(float v) {
    float e, r;
    asm("ex2.approx.f32 %0, %1;" : "=f"(e) : "f"(v * 2.8853900817779268f));
    asm("rcp.approx.f32 %0, %1;" : "=f"(r) : "f"(e + 1.0f));
    return fmaf(-2.0f, r, 1.0f);
}

__device__ __forceinline__ uint32_t pack_h2(float lo, float hi) {
    uint32_t r;
    asm("cvt.rn.f16x2.f32 %0, %1, %2;" : "=r"(r) : "f"(hi), "f"(lo));
    return r;
}

__device__ __forceinline__ void mma16816(float* d,
                                         uint32_t a0, uint32_t a1, uint32_t a2, uint32_t a3,
                                         uint32_t b0, uint32_t b1) {
    asm volatile(
        "mma.sync.aligned.m16n8k16.row.col.f32.f16.f16.f32 "
        "{%0,%1,%2,%3}, {%4,%5,%6,%7}, {%8,%9}, {%0,%1,%2,%3};"
        : "+f"(d[0]), "+f"(d[1]), "+f"(d[2]), "+f"(d[3])
        : "r"(a0), "r"(a1), "r"(a2), "r"(a3), "r"(b0), "r"(b1));
}

#define CP16(dst, src) \
    asm volatile("cp.async.cg.shared.global [%0], [%1], 16;" :: "r"(dst), "l"(src) : "memory")
#define CP_COMMIT() asm volatile("cp.async.commit_group;" ::: "memory")
#define CP_WAIT2()  asm volatile("cp.async.wait_group 2;" ::: "memory")

// ---------------- prepass: fp32 -> permuted fp16 ----------------
__global__ __launch_bounds__(256)
void convert_kernel(const float* __restrict__ src, uint32_t* __restrict__ dst, int nrows) {
    int idx = blockIdx.x * 256 + threadIdx.x;
    if (idx >= nrows * 256) return;
    int r  = idx >> 8;
    int c8 = idx & 255;
    int kb = c8 >> 3;
    int c  = c8 & 7;
    float4 v = *(const float4*)(src + ((size_t)r << 10) + kb * 32 + c * 4);
    uint32_t h01 = pack_h2(v.x, v.y);
    uint32_t h23 = pack_h2(v.z, v.w);
    size_t base = ((size_t)r * 32 + kb) * 16;
    int p0 = 8 * (c & 1) + (c >> 1);
    dst[base + p0]     = h01;
    dst[base + p0 + 4] = h23;
}

// ---------------- hterm = hx @ W_hh^T + b_ih + b_hh (fp32 exact) ----------------
__global__ __launch_bounds__(256)
void hterm_kernel(const float* __restrict__ hx, const float* __restrict__ Whh,
                  const float* __restrict__ bih, const float* __restrict__ bhh) {
    int gw   = (blockIdx.x * blockDim.x + threadIdx.x) >> 5;
    int lane = threadIdx.x & 31;
    if (gw >= H_DIM) return;
    int h = gw;

    float acc[B_DIM];
#pragma unroll
    for (int b = 0; b < B_DIM; ++b) acc[b] = 0.0f;

    const float4* wr = (const float4*)(Whh + (size_t)h * H_DIM);
#pragma unroll
    for (int it = 0; it < H_DIM / 128; ++it) {
        int j = lane + it * 32;
        float4 w4 = wr[j];
#pragma unroll
        for (int b = 0; b < B_DIM; ++b) {
            float4 hv = ((const float4*)(hx + (size_t)b * H_DIM))[j];
            acc[b] += w4.x * hv.x + w4.y * hv.y + w4.z * hv.z + w4.w * hv.w;
        }
    }
#pragma unroll
    for (int b = 0; b < B_DIM; ++b)
#pragma unroll
        for (int o = 16; o > 0; o >>= 1)
            acc[b] += __shfl_xor_sync(0xFFFFFFFFu, acc[b], o);

    if (lane == 0) {
        float bias = bih[h] + bhh[h];
#pragma unroll
        for (int b = 0; b < B_DIM; ++b)
            g_hterm[b * H_DIM + h] = acc[b] + bias;
    }
}

// ---------------- main GEMM + tanh ----------------
// 128 threads = 4 warps in a 2x2 grid, warp tile 64x64 over the 128x128 CTA tile.
__global__ __launch_bounds__(THREADS)
void gemm_tanh_kernel(float* __restrict__ out) {
    extern __shared__ __align__(16) uint32_t sbuf[];   // 64 KB, 4 stages

    int tid  = threadIdx.x;
    int wid  = tid >> 5;
    int lane = tid & 31;
    int g    = lane >> 2;
    int tg   = lane & 3;

    int mb = blockIdx.x >> 3;
    int nb = blockIdx.x & 7;           // 8 consecutive CTAs share x M-tile in L2
    int m0 = mb * BM;
    int n0 = nb * BN;
    int bb = m0 >> 11;

    int warp_m = (wid & 1) * 64;       // 2 warps along M
    int warp_n = (wid >> 1) * 64;      // 2 warps along N

    uint32_t sb = smem_u32(sbuf);

    // producer: one thread per row (128 rows A + 128 rows B), 64B per row per tile
    const uint32_t* srcA = g_xh + (size_t)(m0 + tid) * 512;   // row stride 512 u32
    const uint32_t* srcB = g_wh + (size_t)(n0 + tid) * 512;
    uint32_t dstA = sb + tid * 64;
    uint32_t dstB = dstA + 8192;

    // tile t -> stage t&3 (smem byte offset (t&3)*16384), src offset t*16 u32
#define COPY_TILE(t_imm, soff) do {                                   \
    CP16(dstA + (soff),      srcA + (t_imm) * 16);                    \
    CP16(dstA + (soff) + 16, srcA + (t_imm) * 16 + 4);                \
    CP16(dstA + (soff) + 32, srcA + (t_imm) * 16 + 8);                \
    CP16(dstA + (soff) + 48, srcA + (t_imm) * 16 + 12);               \
    CP16(dstB + (soff),      srcB + (t_imm) * 16);                    \
    CP16(dstB + (soff) + 16, srcB + (t_imm) * 16 + 4);                \
    CP16(dstB + (soff) + 32, srcB + (t_imm) * 16 + 8);                \
    CP16(dstB + (soff) + 48, srcB + (t_imm) * 16 + 12);               \
} while (0)

    COPY_TILE(0, 0);      CP_COMMIT();
    COPY_TILE(1, 16384);  CP_COMMIT();
    COPY_TILE(2, 32768);  CP_COMMIT();

    float acc[4][8][4];
#pragma unroll
    for (int mt = 0; mt < 4; ++mt)
#pragma unroll
        for (int nt = 0; nt < 8; ++nt)
#pragma unroll
            for (int r = 0; r < 4; ++r) acc[mt][nt][r] = 0.0f;

    for (int itb = 0; itb < KIT / 4; ++itb) {
#pragma unroll
        for (int j = 0; j < 4; ++j) {            // stage == j (compile-time)
            CP_WAIT2();
            __syncthreads();

            const uint32_t* sA = sbuf + j * STAGE_U32;
            const uint32_t* sB = sA + 2048;

            uint4 aL[4], aH[4], bV[8];
#pragma unroll
            for (int mt = 0; mt < 4; ++mt) {
                int R = warp_m + mt * 16 + g;
                aL[mt] = *(const uint4*)(sA + R * 16 + 4 * tg);
                aH[mt] = *(const uint4*)(sA + (R + 8) * 16 + 4 * tg);
            }
#pragma unroll
            for (int nt = 0; nt < 8; ++nt)
                bV[nt] = *(const uint4*)(sB + (warp_n + nt * 8 + g) * 16 + 4 * tg);

            int it = itb * 4 + j;
            if (it + 3 < KIT)
                COPY_TILE(j + 3, ((j + 3) & 3) * 16384);
            CP_COMMIT();

#pragma unroll
            for (int mt = 0; mt < 4; ++mt)
#pragma unroll
                for (int nt = 0; nt < 8; ++nt) {
                    mma16816(acc[mt][nt], aL[mt].x, aH[mt].x, aL[mt].y, aH[mt].y,
                             bV[nt].x, bV[nt].y);
                    mma16816(acc[mt][nt], aL[mt].z, aH[mt].z, aL[mt].w, aH[mt].w,
                             bV[nt].z, bV[nt].w);
                }
        }
        // advance source pointers by 4 tiles (64 u32)
        srcA += 64; srcB += 64;
    }

    // ---- epilogue: +hterm, tanh, store ----
    const float* ht = g_hterm + bb * H_DIM + n0;
#pragma unroll
    for (int mt = 0; mt < 4; ++mt) {
        int r0 = m0 + warp_m + mt * 16 + g;
#pragma unroll
        for (int nt = 0; nt < 8; ++nt) {
            int nloc = warp_n + nt * 8 + tg * 2;
            float h0 = __ldg(ht + nloc), h1 = __ldg(ht + nloc + 1);
            float* a = acc[mt][nt];
            float2 v0, v1;
            v0.x = tanh_fast(a[0] + h0);
            v0.y = tanh_fast(a[1] + h1);
            v1.x = tanh_fast(a[2] + h0);
            v1.y = tanh_fast(a[3] + h1);
            *(float2*)(out + (size_t)r0 * H_DIM + n0 + nloc) = v0;
            *(float2*)(out + (size_t)(r0 + 8) * H_DIM + n0 + nloc) = v1;
        }
    }
}

// ---------------- launch ----------------
extern "C" void kernel_launch(void* const* d_in, const int* in_sizes, int n_in,
                              void* d_out, int out_size) {
    const float* x   = (const float*)d_in[0];
    const float* hx  = (const float*)d_in[1];
    const float* Wih = (const float*)d_in[2];
    const float* Whh = (const float*)d_in[3];
    const float* bih = (const float*)d_in[4];
    const float* bhh = (const float*)d_in[5];
    float* out = (float*)d_out;

    uint32_t* xh;  cudaGetSymbolAddress((void**)&xh, g_xh);
    uint32_t* wh;  cudaGetSymbolAddress((void**)&wh, g_wh);

    cudaFuncSetAttribute(gemm_tanh_kernel,
                         cudaFuncAttributeMaxDynamicSharedMemorySize, SMEM_BYTES);

    convert_kernel<<<(M_TOTAL * 256) / 256, 256>>>(x,   xh, M_TOTAL);
    convert_kernel<<<(H_DIM  * 256) / 256, 256>>>(Wih, wh, H_DIM);
    hterm_kernel<<<H_DIM / 8, 256>>>(hx, Whh, bih, bhh);
    gemm_tanh_kernel<<<(M_TOTAL / BM) * (H_DIM / BN), THREADS, SMEM_BYTES>>>(out);
}

// round 9
// speedup vs baseline: 1.4511x; 1.4511x over previous
#include <cuda_runtime.h>
#include <cuda_fp16.h>
#include <cstdint>

#define B_DIM 16
#define S_DIM 2048
#define I_DIM 1024
#define H_DIM 1024
#define M_TOTAL (B_DIM * S_DIM)   // 32768

#define BM 128
#define BN 128
#define KIT 32                    // K iterations of 32 halves each
#define THREADS 256
#define STAGES 4
#define STAGE_U32 4096            // A: 2048 u32 (128x32 half) + B: 2048 u32
#define SMEM_BYTES (STAGES * STAGE_U32 * 4)   // 64 KB dynamic

// Pre-permuted half buffers: row r, k-block kb (32 halves = 16 pairs),
// pair q at u32 position P(q) = 4*(q&3) + (q>>2) within the 16-u32 block.
// Lane tg LDS.128 at offset 4*tg -> pairs {tg, tg+4, tg+8, tg+12} =
// the m16n8k16 A/B fragments for both k-steps.
__device__ uint32_t g_xh[(size_t)M_TOTAL * I_DIM / 2];   // 64 MB
__device__ uint32_t g_wh[(size_t)H_DIM * I_DIM / 2];     // 2 MB
__device__ float    g_hterm[B_DIM * H_DIM];

// ---------------- helpers ----------------
__device__ __forceinline__ uint32_t smem_u32(const void* p) {
    uint32_t a;
    asm("{ .reg .u64 t; cvta.to.shared.u64 t, %1; cvt.u32.u64 %0, t; }" : "=r"(a) : "l"(p));
    return a;
}

__device__ __forceinline__ float tanh_fast(float v) {
    float e, r;
    asm("ex2.approx.f32 %0, %1;" : "=f"(e) : "f"(v * 2.8853900817779268f));
    asm("rcp.approx.f32 %0, %1;" : "=f"(r) : "f"(e + 1.0f));
    return fmaf(-2.0f, r, 1.0f);
}

__device__ __forceinline__ uint32_t pack_h2(float lo, float hi) {
    uint32_t r;
    asm("cvt.rn.f16x2.f32 %0, %1, %2;" : "=r"(r) : "f"(hi), "f"(lo));
    return r;
}

__device__ __forceinline__ void mma16816(float* d,
                                         uint32_t a0, uint32_t a1, uint32_t a2, uint32_t a3,
                                         uint32_t b0, uint32_t b1) {
    asm volatile(
        "mma.sync.aligned.m16n8k16.row.col.f32.f16.f16.f32 "
        "{%0,%1,%2,%3}, {%4,%5,%6,%7}, {%8,%9}, {%0,%1,%2,%3};"
        : "+f"(d[0]), "+f"(d[1]), "+f"(d[2]), "+f"(d[3])
        : "r"(a0), "r"(a1), "r"(a2), "r"(a3), "r"(b0), "r"(b1));
}

#define CP16(dst, src) \
    asm volatile("cp.async.cg.shared.global [%0], [%1], 16;" :: "r"(dst), "l"(src) : "memory")
#define CP_COMMIT() asm volatile("cp.async.commit_group;" ::: "memory")
#define CP_WAIT1()  asm volatile("cp.async.wait_group 1;" ::: "memory")
#define CP_WAIT2()  asm volatile("cp.async.wait_group 2;" ::: "memory")

// ---------------- prepass: fp32 -> permuted fp16 ----------------
__global__ __launch_bounds__(256)
void convert_kernel(const float* __restrict__ src, uint32_t* __restrict__ dst, int nrows) {
    int idx = blockIdx.x * 256 + threadIdx.x;
    if (idx >= nrows * 256) return;
    int r  = idx >> 8;
    int c8 = idx & 255;
    int kb = c8 >> 3;
    int c  = c8 & 7;
    float4 v = *(const float4*)(src + ((size_t)r << 10) + kb * 32 + c * 4);
    uint32_t h01 = pack_h2(v.x, v.y);
    uint32_t h23 = pack_h2(v.z, v.w);
    size_t base = ((size_t)r * 32 + kb) * 16;
    int p0 = 8 * (c & 1) + (c >> 1);
    dst[base + p0]     = h01;
    dst[base + p0 + 4] = h23;
}

// ---------------- hterm = hx @ W_hh^T + b_ih + b_hh (fp32 exact) ----------------
__global__ __launch_bounds__(256)
void hterm_kernel(const float* __restrict__ hx, const float* __restrict__ Whh,
                  const float* __restrict__ bih, const float* __restrict__ bhh) {
    int gw   = (blockIdx.x * blockDim.x + threadIdx.x) >> 5;
    int lane = threadIdx.x & 31;
    if (gw >= H_DIM) return;
    int h = gw;

    float acc[B_DIM];
#pragma unroll
    for (int b = 0; b < B_DIM; ++b) acc[b] = 0.0f;

    const float4* wr = (const float4*)(Whh + (size_t)h * H_DIM);
#pragma unroll
    for (int it = 0; it < H_DIM / 128; ++it) {
        int j = lane + it * 32;
        float4 w4 = wr[j];
#pragma unroll
        for (int b = 0; b < B_DIM; ++b) {
            float4 hv = ((const float4*)(hx + (size_t)b * H_DIM))[j];
            acc[b] += w4.x * hv.x + w4.y * hv.y + w4.z * hv.z + w4.w * hv.w;
        }
    }
#pragma unroll
    for (int b = 0; b < B_DIM; ++b)
#pragma unroll
        for (int o = 16; o > 0; o >>= 1)
            acc[b] += __shfl_xor_sync(0xFFFFFFFFu, acc[b], o);

    if (lane == 0) {
        float bias = bih[h] + bhh[h];
#pragma unroll
        for (int b = 0; b < B_DIM; ++b)
            g_hterm[b * H_DIM + h] = acc[b] + bias;
    }
}

// ---------------- main GEMM + tanh ----------------
// 256 threads, 8 warps in 4(M)x2(N) grid, warp tile 32x64.
// Software-pipelined fragments: A frags for body i loaded at end of body i-1
// (stage i+1 is complete under wait_group 1); B frags stream through a 1-deep
// double buffer inside the nt loop so LDS overlaps MMA.
__global__ __launch_bounds__(THREADS, 2)
void gemm_tanh_kernel(float* __restrict__ out) {
    extern __shared__ __align__(16) uint32_t sbuf[];   // 64 KB, 4 stages

    int tid  = threadIdx.x;
    int wid  = tid >> 5;
    int lane = tid & 31;
    int g    = lane >> 2;
    int tg   = lane & 3;

    int mb = blockIdx.x >> 3;
    int nb = blockIdx.x & 7;           // 8 consecutive CTAs share x M-tile in L2
    int m0 = mb * BM;
    int n0 = nb * BN;
    int bb = m0 >> 11;

    int warp_m = (wid & 3) * 32;
    int warp_n = (wid >> 2) * 64;

    uint32_t sb = smem_u32(sbuf);

    // producer: each thread copies 4x16B per tile (A rows cr, cr+64; B rows cr, cr+64)
    int cr  = tid >> 2;
    int cch = (tid & 3) * 4;
    const uint32_t* srcA0 = g_xh + (size_t)(m0 + cr) * 512 + cch;   // row stride 512 u32
    const uint32_t* srcA1 = srcA0 + (size_t)64 * 512;
    const uint32_t* srcB0 = g_wh + (size_t)(n0 + cr) * 512 + cch;
    const uint32_t* srcB1 = srcB0 + (size_t)64 * 512;
    uint32_t dstA0 = sb + (cr * 16 + cch) * 4;
    uint32_t dstA1 = dstA0 + 64 * 64;
    uint32_t dstB0 = dstA0 + 8192;
    uint32_t dstB1 = dstB0 + 64 * 64;

    // tile t -> stage t&3 (smem byte offset (t&3)*16384), src offset t*16 u32
#define COPY_TILE(t_imm, soff) do {                                   \
    CP16(dstA0 + (soff), srcA0 + (t_imm) * 16);                       \
    CP16(dstA1 + (soff), srcA1 + (t_imm) * 16);                       \
    CP16(dstB0 + (soff), srcB0 + (t_imm) * 16);                       \
    CP16(dstB1 + (soff), srcB1 + (t_imm) * 16);                       \
} while (0)

    COPY_TILE(0, 0);      CP_COMMIT();
    COPY_TILE(1, 16384);  CP_COMMIT();
    COPY_TILE(2, 32768);  CP_COMMIT();

    float acc[2][8][4];
#pragma unroll
    for (int mt = 0; mt < 2; ++mt)
#pragma unroll
        for (int nt = 0; nt < 8; ++nt)
#pragma unroll
            for (int r = 0; r < 4; ++r) acc[mt][nt][r] = 0.0f;

    // ---- prologue: preload body-0 fragments from stage 0 ----
    CP_WAIT2();            // group 0 complete
    __syncthreads();       // visibility of all threads' copies for stage 0

    uint4 aL0, aH0, aL1, aH1, bfrag;
    {
        const uint32_t* sA = sbuf;
        const uint32_t* sB = sbuf + 2048;
        int R = warp_m + g;
        aL0 = *(const uint4*)(sA + R * 16 + 4 * tg);
        aH0 = *(const uint4*)(sA + (R + 8) * 16 + 4 * tg);
        aL1 = *(const uint4*)(sA + (R + 16) * 16 + 4 * tg);
        aH1 = *(const uint4*)(sA + (R + 24) * 16 + 4 * tg);
        bfrag = *(const uint4*)(sB + (warp_n + g) * 16 + 4 * tg);
    }

    for (int itb = 0; itb < KIT / 4; ++itb) {
#pragma unroll
        for (int j = 0; j < 4; ++j) {            // stage == j (compile-time)
            // wait_group 1: stages j AND j+1 of this window are complete
            CP_WAIT1();
            __syncthreads();

            const uint32_t* sB  = sbuf + j * STAGE_U32 + 2048;
            const uint32_t* sAn = sbuf + ((j + 1) & 3) * STAGE_U32;
            const uint32_t* sBn = sAn + 2048;

            int it = itb * 4 + j;
            if (it + 3 < KIT)
                COPY_TILE(j + 3, ((j + 3) & 3) * 16384);
            CP_COMMIT();

            // ---- B-streamed MMA: load bV[nt+1] while computing bV[nt] ----
            uint4 bcur = bfrag;
#pragma unroll
            for (int nt = 0; nt < 8; ++nt) {
                uint4 bnxt;
                if (nt < 7)
                    bnxt = *(const uint4*)(sB + (warp_n + (nt + 1) * 8 + g) * 16 + 4 * tg);
                else
                    bnxt = *(const uint4*)(sBn + (warp_n + g) * 16 + 4 * tg); // next body nt=0
                mma16816(acc[0][nt], aL0.x, aH0.x, aL0.y, aH0.y, bcur.x, bcur.y);
                mma16816(acc[0][nt], aL0.z, aH0.z, aL0.w, aH0.w, bcur.z, bcur.w);
                mma16816(acc[1][nt], aL1.x, aH1.x, aL1.y, aH1.y, bcur.x, bcur.y);
                mma16816(acc[1][nt], aL1.z, aH1.z, aL1.w, aH1.w, bcur.z, bcur.w);
                bcur = bnxt;
            }
            bfrag = bcur;

            // ---- preload next body's A fragments (stage j+1, known complete) ----
            {
                int R = warp_m + g;
                aL0 = *(const uint4*)(sAn + R * 16 + 4 * tg);
                aH0 = *(const uint4*)(sAn + (R + 8) * 16 + 4 * tg);
                aL1 = *(const uint4*)(sAn + (R + 16) * 16 + 4 * tg);
                aH1 = *(const uint4*)(sAn + (R + 24) * 16 + 4 * tg);
            }
        }
        // advance source pointers by 4 tiles (64 u32)
        srcA0 += 64; srcA1 += 64; srcB0 += 64; srcB1 += 64;
    }

    // ---- epilogue: +hterm, tanh, store ----
    const float* ht = g_hterm + bb * H_DIM + n0;
#pragma unroll
    for (int mt = 0; mt < 2; ++mt) {
        int r0 = m0 + warp_m + mt * 16 + g;
#pragma unroll
        for (int nt = 0; nt < 8; ++nt) {
            int nloc = warp_n + nt * 8 + tg * 2;
            float h0 = __ldg(ht + nloc), h1 = __ldg(ht + nloc + 1);
            float* a = acc[mt][nt];
            float2 v0, v1;
            v0.x = tanh_fast(a[0] + h0);
            v0.y = tanh_fast(a[1] + h1);
            v1.x = tanh_fast(a[2] + h0);
            v1.y = tanh_fast(a[3] + h1);
            *(float2*)(out + (size_t)r0 * H_DIM + n0 + nloc) = v0;
            *(float2*)(out + (size_t)(r0 + 8) * H_DIM + n0 + nloc) = v1;
        }
    }
}

// ---------------- launch ----------------
extern "C" void kernel_launch(void* const* d_in, const int* in_sizes, int n_in,
                              void* d_out, int out_size) {
    const float* x   = (const float*)d_in[0];
    const float* hx  = (const float*)d_in[1];
    const float* Wih = (const float*)d_in[2];
    const float* Whh = (const float*)d_in[3];
    const float* bih = (const float*)d_in[4];
    const float* bhh = (const float*)d_in[5];
    float* out = (float*)d_out;

    uint32_t* xh;  cudaGetSymbolAddress((void**)&xh, g_xh);
    uint32_t* wh;  cudaGetSymbolAddress((void**)&wh, g_wh);

    cudaFuncSetAttribute(gemm_tanh_kernel,
                         cudaFuncAttributeMaxDynamicSharedMemorySize, SMEM_BYTES);

    convert_kernel<<<(M_TOTAL * 256) / 256, 256>>>(x,   xh, M_TOTAL);
    convert_kernel<<<(H_DIM  * 256) / 256, 256>>>(Wih, wh, H_DIM);
    hterm_kernel<<<H_DIM / 8, 256>>>(hx, Whh, bih, bhh);
    gemm_tanh_kernel<<<(M_TOTAL / BM) * (H_DIM / BN), THREADS, SMEM_BYTES>>>(out);
}